// round 15
// baseline (speedup 1.0000x reference)
#include <cuda_runtime.h>
#include <cuda_fp16.h>
#include <math.h>
#include <stdint.h>

#define N_TOK   4096     // B * S
#define DMODEL  1024
#define DFF     4096
#define NHEAD   16
#define DK      64
#define SEQ     2048
#define BATCH   2
#define QKV_M   3072

// ---------------- scratch (static device globals; no allocation) ----------------
#define WQO 0
#define WKO (1u << 20)
#define WVO (2u << 20)
#define WOO (3u << 20)
#define W1O (4u << 20)
#define W2O (8u << 20)
__device__ __half g_w  [12u << 20];                 // weights: fp16, [outfeat][K]
__device__ __half g_hh [N_TOK * DMODEL];            // LN out (single plane)
__device__ __half g_qkvh[(size_t)N_TOK * QKV_M];
__device__ __half g_qkvl[(size_t)N_TOK * QKV_M];    // lo plane (attention Q needs it)
__device__ __half g_oh [N_TOK * DMODEL];
__device__ __half g_fh [(size_t)N_TOK * DFF];
__device__ float g_x1[N_TOK * DMODEL];
__device__ float g_b3[QKV_M];

// ---------------- helpers ----------------
__device__ __forceinline__ uint32_t smem_u32(const void* p) {
    uint32_t a;
    asm("{ .reg .u64 t; cvta.to.shared.u64 t, %1; cvt.u32.u64 %0, t; }" : "=r"(a) : "l"(p));
    return a;
}
__device__ __forceinline__ void cp16(uint32_t s, const void* g) {
    asm volatile("cp.async.cg.shared.global [%0], [%1], 16;" :: "r"(s), "l"(g));
}
__device__ __forceinline__ void cp_commit() { asm volatile("cp.async.commit_group;"); }
__device__ __forceinline__ void cp_wait4()  { asm volatile("cp.async.wait_group 4;"); }
__device__ __forceinline__ void cp_wait1()  { asm volatile("cp.async.wait_group 1;"); }
__device__ __forceinline__ void cp_wait0()  { asm volatile("cp.async.wait_group 0;"); }
__device__ __forceinline__ void ldsm4(uint32_t* r, uint32_t addr) {
    asm volatile("ldmatrix.sync.aligned.m8n8.x4.shared.b16 {%0,%1,%2,%3}, [%4];"
                 : "=r"(r[0]), "=r"(r[1]), "=r"(r[2]), "=r"(r[3]) : "r"(addr));
}
__device__ __forceinline__ void ldsm4t(uint32_t* r, uint32_t addr) {
    asm volatile("ldmatrix.sync.aligned.m8n8.x4.trans.shared.b16 {%0,%1,%2,%3}, [%4];"
                 : "=r"(r[0]), "=r"(r[1]), "=r"(r[2]), "=r"(r[3]) : "r"(addr));
}
__device__ __forceinline__ void mma_f16(float* c, const uint32_t* a, uint32_t b0, uint32_t b1) {
    asm volatile("mma.sync.aligned.m16n8k16.row.col.f32.f16.f16.f32 "
                 "{%0,%1,%2,%3}, {%4,%5,%6,%7}, {%8,%9}, {%0,%1,%2,%3};"
                 : "+f"(c[0]), "+f"(c[1]), "+f"(c[2]), "+f"(c[3])
                 : "r"(a[0]), "r"(a[1]), "r"(a[2]), "r"(a[3]), "r"(b0), "r"(b1));
}
__device__ __forceinline__ uint32_t f2h2(float a, float b) {
    __half2 h = __floats2half2_rn(a, b);
    return *reinterpret_cast<uint32_t*>(&h);
}
// 2^y on the FMA pipe (clamped below -125). rel err ~1e-7.
__device__ __forceinline__ float fexp2(float y) {
    y = fmaxf(y, -125.f);
    float r = y + 12582912.f;
    float f = y - (r - 12582912.f);
    int n = __float_as_int(r) - 0x4B400000;
    float p = 0.0013333558f;
    p = fmaf(p, f, 0.0096181291f);
    p = fmaf(p, f, 0.055504109f);
    p = fmaf(p, f, 0.24022651f);
    p = fmaf(p, f, 0.69314718f);
    p = fmaf(p, f, 1.0f);
    return p * __int_as_float((n + 127) << 23);
}
// exact-erf GELU via Abramowitz-Stegun 3-term (abs err <= 2.5e-5 on erf).
__device__ __forceinline__ float fgelu(float x) {
    float z = fabsf(x) * 0.70710678f;
    float r;
    asm("rcp.approx.f32 %0, %1;" : "=f"(r) : "f"(fmaf(0.47047f, z, 1.0f)));
    float e = fexp2(-1.44269504f * z * z);
    float p = r * fmaf(r, fmaf(r, 0.7478556f, -0.0958798f), 0.3480242f);
    float er = fmaf(-p, e, 1.0f);
    float phi = fmaf(copysignf(0.5f, x), er, 0.5f);
    return x * phi;
}

// ---------------- LayerNorm (fp16 single-plane output) ----------------
__global__ void __launch_bounds__(256) ln_kernel(const float* __restrict__ x,
                                                 const float* __restrict__ gamma,
                                                 const float* __restrict__ beta,
                                                 __half* __restrict__ ohi) {
    int row = blockIdx.x;
    int t = threadIdx.x;
    const float4 v = reinterpret_cast<const float4*>(x + (size_t)row * DMODEL)[t];
    float s  = v.x + v.y + v.z + v.w;
    float sq = v.x * v.x + v.y * v.y + v.z * v.z + v.w * v.w;
    #pragma unroll
    for (int o = 16; o; o >>= 1) {
        s  += __shfl_xor_sync(0xFFFFFFFFu, s,  o);
        sq += __shfl_xor_sync(0xFFFFFFFFu, sq, o);
    }
    __shared__ float ss[8], ssq[8];
    __shared__ float s_mean, s_rstd;
    int wid = t >> 5, lane = t & 31;
    if (lane == 0) { ss[wid] = s; ssq[wid] = sq; }
    __syncthreads();
    if (t == 0) {
        float ts = 0.f, tq = 0.f;
        #pragma unroll
        for (int i = 0; i < 8; i++) { ts += ss[i]; tq += ssq[i]; }
        float mean = ts * (1.0f / DMODEL);
        float var  = tq * (1.0f / DMODEL) - mean * mean;
        s_mean = mean;
        s_rstd = rsqrtf(var + 1e-5f);
    }
    __syncthreads();
    float mean = s_mean, rstd = s_rstd;
    float4 g4 = reinterpret_cast<const float4*>(gamma)[t];
    float4 b4 = reinterpret_cast<const float4*>(beta)[t];
    float o0 = (v.x - mean) * rstd * g4.x + b4.x;
    float o1 = (v.y - mean) * rstd * g4.y + b4.y;
    float o2 = (v.z - mean) * rstd * g4.z + b4.z;
    float o3 = (v.w - mean) * rstd * g4.w + b4.w;
    size_t idx = (size_t)row * DMODEL + t * 4;
    *reinterpret_cast<__half2*>(ohi + idx)     = __floats2half2_rn(o0, o1);
    *reinterpret_cast<__half2*>(ohi + idx + 2) = __floats2half2_rn(o2, o3);
}

// ---------------- weights transpose + fp16 convert + biascat (single launch) ----------
__global__ void __launch_bounds__(256) wsplit_all(const float* __restrict__ Wq,
                                                  const float* __restrict__ Wk,
                                                  const float* __restrict__ Wv,
                                                  const float* __restrict__ Wo,
                                                  const float* __restrict__ W1,
                                                  const float* __restrict__ W2,
                                                  __half* __restrict__ out,
                                                  const float* __restrict__ bq,
                                                  const float* __restrict__ bk,
                                                  const float* __restrict__ bv,
                                                  float* __restrict__ b3) {
    __shared__ float tile[32][33];
    int id = blockIdx.x;
    if (id >= 12288) {    // biascat tail blocks
        int i = (id - 12288) * 256 + threadIdx.x;
        float v = (i < 1024) ? bq[i] : (i < 2048) ? bk[i - 1024] : bv[i - 2048];
        b3[i] = v;
        return;
    }
    const float* W;
    int K, M, n0, k0;
    uint32_t base;
    if (id < 4096) {
        int wsel = id >> 10, local = id & 1023;
        K = M = 1024;
        n0 = (local & 31) * 32; k0 = (local >> 5) * 32;
        W = (wsel == 0) ? Wq : (wsel == 1) ? Wk : (wsel == 2) ? Wv : Wo;
        base = (uint32_t)wsel << 20;
    } else if (id < 8192) {
        int local = id - 4096;
        K = 1024; M = 4096;
        n0 = (local & 127) * 32; k0 = (local >> 7) * 32;
        W = W1; base = W1O;
    } else {
        int local = id - 8192;
        K = 4096; M = 1024;
        n0 = (local & 31) * 32; k0 = (local >> 5) * 32;
        W = W2; base = W2O;
    }
    int tx = threadIdx.x & 31, ty = threadIdx.x >> 5;
    #pragma unroll
    for (int i = 0; i < 4; i++)
        tile[ty + 8 * i][tx] = W[(size_t)(k0 + ty + 8 * i) * M + n0 + tx];
    __syncthreads();
    #pragma unroll
    for (int i = 0; i < 4; i++) {
        float x = tile[tx][ty + 8 * i];
        out[(size_t)base + (size_t)(n0 + ty + 8 * i) * K + k0 + tx] = __float2half_rn(x);
    }
}

#define GEMM_SMEM (6 * 16384)

// ---------------- QKV GEMM: 4 warps, 64x64 warp tiles ----------------
__global__ void __launch_bounds__(128, 2) gemm_qkv4(const __half* __restrict__ Ah,
                                                    const __half* __restrict__ Bh,
                                                    const float* __restrict__ bias,
                                                    __half* __restrict__ Chi,
                                                    __half* __restrict__ Clo,
                                                    int K, int M) {
    extern __shared__ char smc[];
    uint32_t sb = smem_u32(smc);
    int t = threadIdx.x, lane = t & 31, wid = t >> 5;
    int wr = wid & 1, wc = wid >> 1;
    int m0 = blockIdx.x * 128;
    size_t row0 = (size_t)blockIdx.y * 128;

    int lr = t >> 2, lq = t & 3;
    uint32_t sOl[4];
    #pragma unroll
    for (int i = 0; i < 4; i++) {
        int row = lr + i * 32;
        sOl[i] = (uint32_t)(row * 64 + ((lq ^ ((row >> 1) & 3)) << 4));
    }
    const __half* gA = Ah + (row0 + lr) * (size_t)K + lq * 8;
    const __half* gB = Bh + (size_t)(m0 + lr) * K + lq * 8;

    int g = lane >> 3, l7 = lane & 7;
    uint32_t aRO[4], aSW[4];
    #pragma unroll
    for (int mt = 0; mt < 4; mt++) {
        int arow = wr * 64 + mt * 16 + l7 + ((g & 1) << 3);
        aRO[mt] = (uint32_t)(arow * 64);
        aSW[mt] = (uint32_t)((arow >> 1) & 3);
    }
    uint32_t aKH = (uint32_t)(g >> 1);
    int brow_base = wc * 64 + ((g >> 1) << 3) + l7;
    uint32_t bKH = (uint32_t)(g & 1);

    float acc[4][8][4];
    #pragma unroll
    for (int i = 0; i < 4; i++)
        #pragma unroll
        for (int j = 0; j < 8; j++)
            #pragma unroll
            for (int u = 0; u < 4; u++) acc[i][j][u] = 0.f;

    int NC = K >> 5;
    #pragma unroll
    for (int pk = 0; pk < 5; pk++) {
        uint32_t bb = sb + (uint32_t)pk * 16384u;
        int ko = pk * 32;
        #pragma unroll
        for (int i = 0; i < 4; i++) {
            cp16(bb + sOl[i],        gA + (size_t)i * 32 * K + ko);
            cp16(bb + 8192 + sOl[i], gB + (size_t)i * 32 * K + ko);
        }
        cp_commit();
    }

    int stage = 0, nstage = 5;
    for (int kt = 0; kt < NC; kt++) {
        cp_wait4();
        __syncthreads();
        if (kt + 5 < NC) {
            uint32_t bb = sb + (uint32_t)nstage * 16384u;
            int ko = (kt + 5) * 32;
            #pragma unroll
            for (int i = 0; i < 4; i++) {
                cp16(bb + sOl[i],        gA + (size_t)i * 32 * K + ko);
                cp16(bb + 8192 + sOl[i], gB + (size_t)i * 32 * K + ko);
            }
        }
        cp_commit();

        uint32_t bb = sb + (uint32_t)stage * 16384u;
        #pragma unroll
        for (int ks = 0; ks < 2; ks++) {
            uint32_t ac = (uint32_t)(ks * 2) + aKH;
            uint32_t af[4][4];
            #pragma unroll
            for (int mt = 0; mt < 4; mt++)
                ldsm4(af[mt], bb + aRO[mt] + ((ac ^ aSW[mt]) << 4));
            #pragma unroll
            for (int nh = 0; nh < 4; nh++) {
                int brow = brow_base + nh * 16;
                uint32_t bu = (uint32_t)(ks * 2) + bKH;
                uint32_t boff = (uint32_t)(brow * 64) + ((bu ^ (uint32_t)((brow >> 1) & 3)) << 4);
                uint32_t bh[4];
                ldsm4(bh, bb + 8192 + boff);
                #pragma unroll
                for (int mt = 0; mt < 4; mt++)
                    #pragma unroll
                    for (int s = 0; s < 2; s++)
                        mma_f16(acc[mt][nh * 2 + s], af[mt], bh[s * 2], bh[s * 2 + 1]);
            }
        }
        stage = (stage == 5) ? 0 : stage + 1;
        nstage = (nstage == 5) ? 0 : nstage + 1;
    }

    #pragma unroll
    for (int mt = 0; mt < 4; mt++) {
        size_t rbase = row0 + wr * 64 + mt * 16 + (lane >> 2);
        #pragma unroll
        for (int nt = 0; nt < 8; nt++) {
            int col = m0 + wc * 64 + nt * 8 + (lane & 3) * 2;
            float b0 = bias[col], b1 = bias[col + 1];
            #pragma unroll
            for (int half = 0; half < 2; half++) {
                size_t row = rbase + half * 8;
                float v0 = acc[mt][nt][half * 2 + 0] + b0;
                float v1 = acc[mt][nt][half * 2 + 1] + b1;
                __half2 hp = __floats2half2_rn(v0, v1);
                __half2 lp = __floats2half2_rn(v0 - __low2float(hp),
                                               v1 - __high2float(hp));
                *reinterpret_cast<__half2*>(Chi + row * M + col) = hp;
                *reinterpret_cast<__half2*>(Clo + row * M + col) = lp;
            }
        }
    }
}

// ---------------- 8-warp GEMM: 32x64 tiles (Wo / FFN1 / FFN2) ----------------
// SPLIT: 0 = fp32 out (+res), 2 = fp16 hi plane only
template<int GELU, int RES, int SPLIT>
__global__ void __launch_bounds__(256, 2) gemm_mma(const __half* __restrict__ Ah,
                                                   const __half* __restrict__ Bh,
                                                   const float* __restrict__ bias,
                                                   const float* __restrict__ res,
                                                   float* __restrict__ C,
                                                   __half* __restrict__ Chi,
                                                   int K, int M) {
    extern __shared__ char smc[];
    uint32_t sb = smem_u32(smc);
    int t = threadIdx.x, lane = t & 31, wid = t >> 5;
    int wr = wid & 3, wc = wid >> 2;
    int m0 = blockIdx.x * 128;
    size_t row0 = (size_t)blockIdx.y * 128;

    int r0 = t >> 2, cq = t & 3;
    int r1 = r0 + 64;
    uint32_t sO0 = (uint32_t)(r0 * 64 + ((cq ^ ((r0 >> 1) & 3)) << 4));
    uint32_t sO1 = (uint32_t)(r1 * 64 + ((cq ^ ((r1 >> 1) & 3)) << 4));
    const __half* gA0 = Ah + (row0 + r0) * (size_t)K + cq * 8;
    const __half* gA1 = Ah + (row0 + r1) * (size_t)K + cq * 8;
    const __half* gB0 = Bh + (size_t)(m0 + r0) * K + cq * 8;
    const __half* gB1 = Bh + (size_t)(m0 + r1) * K + cq * 8;

    int g = lane >> 3, l7 = lane & 7;
    int arow0 = wr * 32 + l7 + ((g & 1) << 3);
    int arow1 = arow0 + 16;
    uint32_t aRO0 = (uint32_t)(arow0 * 64), aSW0 = (uint32_t)((arow0 >> 1) & 3);
    uint32_t aRO1 = (uint32_t)(arow1 * 64), aSW1 = (uint32_t)((arow1 >> 1) & 3);
    uint32_t aKH = (uint32_t)(g >> 1);
    int brow_base = wc * 64 + ((g >> 1) << 3) + l7;
    uint32_t bKH = (uint32_t)(g & 1);

    float acc[2][8][4];
    #pragma unroll
    for (int i = 0; i < 2; i++)
        #pragma unroll
        for (int j = 0; j < 8; j++)
            #pragma unroll
            for (int u = 0; u < 4; u++) acc[i][j][u] = 0.f;

    int NC = K >> 5;
    #pragma unroll
    for (int pk = 0; pk < 5; pk++) {
        uint32_t bb = sb + (uint32_t)pk * 16384u;
        int ko = pk * 32;
        cp16(bb + sO0,        gA0 + ko); cp16(bb + sO1,        gA1 + ko);
        cp16(bb + 8192 + sO0, gB0 + ko); cp16(bb + 8192 + sO1, gB1 + ko);
        cp_commit();
    }

    int stage = 0, nstage = 5;
    for (int kt = 0; kt < NC; kt++) {
        cp_wait4();
        __syncthreads();
        if (kt + 5 < NC) {
            uint32_t bb = sb + (uint32_t)nstage * 16384u;
            int ko = (kt + 5) * 32;
            cp16(bb + sO0,        gA0 + ko); cp16(bb + sO1,        gA1 + ko);
            cp16(bb + 8192 + sO0, gB0 + ko); cp16(bb + 8192 + sO1, gB1 + ko);
        }
        cp_commit();

        uint32_t bb = sb + (uint32_t)stage * 16384u;
        #pragma unroll
        for (int ks = 0; ks < 2; ks++) {
            uint32_t ac = (uint32_t)(ks * 2) + aKH;
            uint32_t ah0[4], ah1[4];
            ldsm4(ah0, bb + aRO0 + ((ac ^ aSW0) << 4));
            ldsm4(ah1, bb + aRO1 + ((ac ^ aSW1) << 4));
            #pragma unroll
            for (int nh = 0; nh < 4; nh++) {
                int brow = brow_base + nh * 16;
                uint32_t bRO = (uint32_t)(brow * 64), bSW = (uint32_t)((brow >> 1) & 3);
                uint32_t bc = (uint32_t)(ks * 2) + bKH;
                uint32_t boff = bRO + ((bc ^ bSW) << 4);
                uint32_t bh[4];
                ldsm4(bh, bb + 8192 + boff);
                #pragma unroll
                for (int s = 0; s < 2; s++) {
                    mma_f16(acc[0][nh * 2 + s], ah0, bh[s * 2], bh[s * 2 + 1]);
                    mma_f16(acc[1][nh * 2 + s], ah1, bh[s * 2], bh[s * 2 + 1]);
                }
            }
        }
        stage = (stage == 5) ? 0 : stage + 1;
        nstage = (nstage == 5) ? 0 : nstage + 1;
    }

    #pragma unroll
    for (int mt = 0; mt < 2; mt++) {
        size_t rbase = row0 + wr * 32 + mt * 16 + (lane >> 2);
        #pragma unroll
        for (int nt = 0; nt < 8; nt++) {
            int col = m0 + wc * 64 + nt * 8 + (lane & 3) * 2;
            float b0 = bias[col], b1 = bias[col + 1];
            #pragma unroll
            for (int half = 0; half < 2; half++) {
                size_t row = rbase + half * 8;
                float v0 = acc[mt][nt][half * 2 + 0] + b0;
                float v1 = acc[mt][nt][half * 2 + 1] + b1;
                if (GELU) { v0 = fgelu(v0); v1 = fgelu(v1); }
                if (RES) {
                    float2 r2 = *reinterpret_cast<const float2*>(res + row * M + col);
                    v0 += r2.x; v1 += r2.y;
                }
                if (SPLIT == 2) {
                    *reinterpret_cast<__half2*>(Chi + row * M + col) = __floats2half2_rn(v0, v1);
                } else {
                    *reinterpret_cast<float2*>(C + row * M + col) = make_float2(v0, v1);
                }
            }
        }
    }
}

// ---------------- mma.sync causal flash attention: 8 warps x 16 q-rows ----------------
#define ATT_SMEM 65536
#define SCALE_L2E 0.18033688f   // 0.125 * log2(e)

__global__ void __launch_bounds__(256) attn_mma(const __half* __restrict__ qkvh,
                                                const __half* __restrict__ qkvl,
                                                __half* __restrict__ ohi) {
    extern __shared__ char smc[];
    uint32_t sb = smem_u32(smc);
    int t = threadIdx.x, lane = t & 31, w = t >> 5;
    int g = lane >> 3, l7 = lane & 7;
    int bh = blockIdx.y;
    int b = bh >> 4, h = bh & 15;
    int qt = (SEQ / 128 - 1) - blockIdx.x;
    int qb = qt * 128;
    size_t tok0 = (size_t)(b * SEQ + qb);

    {
        #pragma unroll
        for (int i = 0; i < 8; i++) {
            int c = t + i * 256;
            int plane = c >> 10, rem = c & 1023;
            int row = rem >> 3, u = rem & 7;
            uint32_t so = (uint32_t)(plane * 16384 + row * 128 + ((u ^ (row & 7)) << 4));
            const __half* gp = (plane ? qkvl : qkvh) + (tok0 + row) * QKV_M + h * 64 + u * 8;
            cp16(sb + so, gp);
        }
        size_t ktok = (size_t)(b * SEQ);
        #pragma unroll
        for (int i = 0; i < 4; i++) {
            int c = t + i * 256;
            int plane = c >> 9, rem = c & 511;   // 0=K, 1=V
            int row = rem >> 3, u = rem & 7;
            uint32_t so = (uint32_t)(32768 + plane * 8192 + row * 128 + ((u ^ (row & 7)) << 4));
            const __half* gp = qkvh + (ktok + row) * QKV_M + 1024 + plane * 1024 + h * 64 + u * 8;
            cp16(sb + so, gp);
        }
        cp_commit();
    }

    uint32_t qah[4][4], qal[4][4];
    float m0 = -1e30f, m1 = -1e30f, l0 = 0.f, l1 = 0.f;
    float o[8][4];
    #pragma unroll
    for (int j = 0; j < 8; j++)
        #pragma unroll
        for (int u = 0; u < 4; u++) o[j][u] = 0.f;

    int q0g = qb + w * 16 + (lane >> 2);
    int q1g = q0g + 8;
    int qwmax = qb + w * 16 + 15;      // max q-row this warp owns

    int ntiles = 2 * qt + 2;
    for (int kt = 0; kt < ntiles; kt++) {
        int k0 = kt * 64;
        if (kt + 1 < ntiles) {
            uint32_t bufb = 32768u + (uint32_t)((kt + 1) & 1) * 16384u;
            size_t ktok = (size_t)(b * SEQ + (kt + 1) * 64);
            #pragma unroll
            for (int i = 0; i < 4; i++) {
                int c = t + i * 256;
                int plane = c >> 9, rem = c & 511;
                int row = rem >> 3, u = rem & 7;
                uint32_t so = bufb + (uint32_t)(plane * 8192 + row * 128 + ((u ^ (row & 7)) << 4));
                const __half* gp = qkvh + (ktok + row) * QKV_M + 1024 + plane * 1024 + h * 64 + u * 8;
                cp16(sb + so, gp);
            }
            cp_commit();
            cp_wait1();
        } else {
            cp_wait0();
        }
        __syncthreads();

        if (kt == 0) {
            int arow = w * 16 + (lane & 15);
            uint32_t aro = (uint32_t)(arow * 128);
            uint32_t asw = (uint32_t)(arow & 7);
            #pragma unroll
            for (int ks = 0; ks < 4; ks++) {
                uint32_t u = (uint32_t)(ks * 2) + (uint32_t)(lane >> 4);
                uint32_t off = aro + ((u ^ asw) << 4);
                ldsm4(qah[ks], sb + off);
                ldsm4(qal[ks], sb + 16384 + off);
            }
        }

        bool diag = (kt >= 2 * qt);
        // fully-masked warp tile: all of this warp's queries precede every key (exact skip)
        if (diag && k0 > qwmax) {
            __syncthreads();
            continue;
        }

        uint32_t kvb = sb + 32768u + (uint32_t)(kt & 1) * 16384u;

        float s[8][4];
        #pragma unroll
        for (int j = 0; j < 8; j++)
            #pragma unroll
            for (int u = 0; u < 4; u++) s[j][u] = 0.f;

        #pragma unroll
        for (int nh = 0; nh < 4; nh++) {
            int brow = nh * 16 + ((g >> 1) << 3) + l7;
            uint32_t bro = (uint32_t)(brow * 128);
            uint32_t bsw = (uint32_t)(brow & 7);
            #pragma unroll
            for (int ks = 0; ks < 4; ks++) {
                uint32_t u = (uint32_t)(ks * 2) + (uint32_t)(g & 1);
                uint32_t off = bro + ((u ^ bsw) << 4);
                uint32_t bhf[4];
                ldsm4(bhf, kvb + off);
                float* c0 = s[nh * 2];
                float* c1 = s[nh * 2 + 1];
                mma_f16(c0, qah[ks], bhf[0], bhf[1]);
                mma_f16(c0, qal[ks], bhf[0], bhf[1]);
                mma_f16(c1, qah[ks], bhf[2], bhf[3]);
                mma_f16(c1, qal[ks], bhf[2], bhf[3]);
            }
        }

        float mx0 = -1e30f, mx1 = -1e30f;
        #pragma unroll
        for (int j = 0; j < 8; j++) {
            int kb = k0 + j * 8 + ((lane & 3) << 1);
            float y0 = s[j][0] * SCALE_L2E;
            float y1 = s[j][1] * SCALE_L2E;
            float y2 = s[j][2] * SCALE_L2E;
            float y3 = s[j][3] * SCALE_L2E;
            if (diag) {
                if (kb     > q0g) y0 = -1e30f;
                if (kb + 1 > q0g) y1 = -1e30f;
                if (kb     > q1g) y2 = -1e30f;
                if (kb + 1 > q1g) y3 = -1e30f;
            }
            s[j][0] = y0; s[j][1] = y1; s[j][2] = y2; s[j][3] = y3;
            mx0 = fmaxf(mx0, fmaxf(y0, y1));
            mx1 = fmaxf(mx1, fmaxf(y2, y3));
        }
        mx0 = fmaxf(mx0, __shfl_xor_sync(0xFFFFFFFFu, mx0, 1));
        mx0 = fmaxf(mx0, __shfl_xor_sync(0xFFFFFFFFu, mx0, 2));
        mx1 = fmaxf(mx1, __shfl_xor_sync(0xFFFFFFFFu, mx1, 1));
        mx1 = fmaxf(mx1, __shfl_xor_sync(0xFFFFFFFFu, mx1, 2));

        float m0n = fmaxf(m0, mx0), m1n = fmaxf(m1, mx1);
        float corr0 = fexp2(m0 - m0n), corr1 = fexp2(m1 - m1n);
        m0 = m0n; m1 = m1n;

        float rs0 = 0.f, rs1 = 0.f;
        #pragma unroll
        for (int j = 0; j < 8; j++) {
            float p0 = fexp2(s[j][0] - m0);
            float p1 = fexp2(s[j][1] - m0);
            float p2 = fexp2(s[j][2] - m1);
            float p3 = fexp2(s[j][3] - m1);
            s[j][0] = p0; s[j][1] = p1; s[j][2] = p2; s[j][3] = p3;
            rs0 += p0 + p1; rs1 += p2 + p3;
        }
        rs0 += __shfl_xor_sync(0xFFFFFFFFu, rs0, 1);
        rs0 += __shfl_xor_sync(0xFFFFFFFFu, rs0, 2);
        rs1 += __shfl_xor_sync(0xFFFFFFFFu, rs1, 1);
        rs1 += __shfl_xor_sync(0xFFFFFFFFu, rs1, 2);
        l0 = l0 * corr0 + rs0;
        l1 = l1 * corr1 + rs1;
        #pragma unroll
        for (int j = 0; j < 8; j++) {
            o[j][0] *= corr0; o[j][1] *= corr0;
            o[j][2] *= corr1; o[j][3] *= corr1;
        }

        #pragma unroll
        for (int ks2 = 0; ks2 < 4; ks2++) {
            int j0 = ks2 * 2, j1 = j0 + 1;
            uint32_t aPh[4];
            aPh[0] = f2h2(s[j0][0], s[j0][1]);
            aPh[1] = f2h2(s[j0][2], s[j0][3]);
            aPh[2] = f2h2(s[j1][0], s[j1][1]);
            aPh[3] = f2h2(s[j1][2], s[j1][3]);

            int vrow = ks2 * 16 + ((g & 1) << 3) + l7;
            uint32_t vro = (uint32_t)(vrow * 128);
            uint32_t vsw = (uint32_t)(vrow & 7);
            #pragma unroll
            for (int dh = 0; dh < 4; dh++) {
                uint32_t u = (uint32_t)(dh * 2) + (uint32_t)(g >> 1);
                uint32_t off = vro + ((u ^ vsw) << 4);
                uint32_t vhf[4];
                ldsm4t(vhf, kvb + 8192 + off);
                mma_f16(o[dh * 2],     aPh, vhf[0], vhf[1]);
                mma_f16(o[dh * 2 + 1], aPh, vhf[2], vhf[3]);
            }
        }
        __syncthreads();
    }

    float inv0 = 1.0f / l0, inv1 = 1.0f / l1;
    size_t r0o = ((size_t)(b * SEQ) + q0g) * DMODEL + h * 64;
    size_t r1o = ((size_t)(b * SEQ) + q1g) * DMODEL + h * 64;
    #pragma unroll
    for (int j = 0; j < 8; j++) {
        int col = j * 8 + (lane & 3) * 2;
        *reinterpret_cast<__half2*>(ohi + r0o + col) =
            __floats2half2_rn(o[j][0] * inv0, o[j][1] * inv0);
        *reinterpret_cast<__half2*>(ohi + r1o + col) =
            __floats2half2_rn(o[j][2] * inv1, o[j][3] * inv1);
    }
}

// ---------------- launch ----------------
extern "C" void kernel_launch(void* const* d_in, const int* in_sizes, int n_in,
                              void* d_out, int out_size) {
    const float* x    = (const float*)d_in[0];
    const float* ln1g = (const float*)d_in[1];
    const float* ln1b = (const float*)d_in[2];
    const float* Wq   = (const float*)d_in[3];
    const float* bq   = (const float*)d_in[4];
    const float* Wk   = (const float*)d_in[5];
    const float* bk   = (const float*)d_in[6];
    const float* Wv   = (const float*)d_in[7];
    const float* bv   = (const float*)d_in[8];
    const float* Wo   = (const float*)d_in[9];
    const float* bo   = (const float*)d_in[10];
    const float* ln2g = (const float*)d_in[11];
    const float* ln2b = (const float*)d_in[12];
    const float* W1   = (const float*)d_in[13];
    const float* b1   = (const float*)d_in[14];
    const float* W2   = (const float*)d_in[15];
    const float* b2   = (const float*)d_in[16];
    float* out = (float*)d_out;

    __half *w, *hh, *qkvh, *qkvl, *oh, *fh;
    float *x1, *b3;
    cudaGetSymbolAddress((void**)&w,    g_w);
    cudaGetSymbolAddress((void**)&hh,   g_hh);
    cudaGetSymbolAddress((void**)&qkvh, g_qkvh);
    cudaGetSymbolAddress((void**)&qkvl, g_qkvl);
    cudaGetSymbolAddress((void**)&oh,   g_oh);
    cudaGetSymbolAddress((void**)&fh,   g_fh);
    cudaGetSymbolAddress((void**)&x1,   g_x1);
    cudaGetSymbolAddress((void**)&b3,   g_b3);

    static int attr_set = 0;
    if (!attr_set) {
        cudaFuncSetAttribute(attn_mma, cudaFuncAttributeMaxDynamicSharedMemorySize, ATT_SMEM);
        cudaFuncSetAttribute(gemm_qkv4, cudaFuncAttributeMaxDynamicSharedMemorySize, GEMM_SMEM);
        cudaFuncSetAttribute(gemm_mma<0, 1, 0>, cudaFuncAttributeMaxDynamicSharedMemorySize, GEMM_SMEM);
        cudaFuncSetAttribute(gemm_mma<1, 0, 2>, cudaFuncAttributeMaxDynamicSharedMemorySize, GEMM_SMEM);
        attr_set = 1;
    }

    wsplit_all<<<12300, 256>>>(Wq, Wk, Wv, Wo, W1, W2, w, bq, bk, bv, b3);

    // --- attention sublayer ---
    ln_kernel<<<N_TOK, 256>>>(x, ln1g, ln1b, hh);
    gemm_qkv4<<<dim3(QKV_M / 128, 32), 128, GEMM_SMEM>>>(
        hh, w + WQO, b3, qkvh, qkvl, DMODEL, QKV_M);
    attn_mma<<<dim3(SEQ / 128, NHEAD * BATCH), 256, ATT_SMEM>>>(qkvh, qkvl, oh);
    gemm_mma<0, 1, 0><<<dim3(8, 32), 256, GEMM_SMEM>>>(
        oh, w + WOO, bo, x, x1, nullptr, DMODEL, DMODEL);

    // --- FFN sublayer ---
    ln_kernel<<<N_TOK, 256>>>(x1, ln2g, ln2b, hh);
    gemm_mma<1, 0, 2><<<dim3(32, 32), 256, GEMM_SMEM>>>(
        hh, w + W1O, b1, nullptr, nullptr, fh, DMODEL, DFF);
    gemm_mma<0, 1, 0><<<dim3(8, 32), 256, GEMM_SMEM>>>(
        fh, w + W2O, b2, x1, out, nullptr, DFF, DMODEL);
}

// round 16
// speedup vs baseline: 1.0178x; 1.0178x over previous
#include <cuda_runtime.h>
#include <cuda_fp16.h>
#include <math.h>
#include <stdint.h>

#define N_TOK   4096     // B * S
#define DMODEL  1024
#define DFF     4096
#define NHEAD   16
#define DK      64
#define SEQ     2048
#define BATCH   2
#define QKV_M   3072

// ---------------- scratch (static device globals; no allocation) ----------------
#define WQO 0
#define WKO (1u << 20)
#define WVO (2u << 20)
#define WOO (3u << 20)
#define W1O (4u << 20)
#define W2O (8u << 20)
__device__ __half g_w  [12u << 20];                 // weights: fp16, [outfeat][K]
__device__ __half g_hh [N_TOK * DMODEL];            // LN out (single plane)
__device__ __half g_qkvh[(size_t)N_TOK * QKV_M];
__device__ __half g_qkvl[(size_t)N_TOK * QKV_M];    // lo plane (attention Q needs it)
__device__ __half g_oh [N_TOK * DMODEL];
__device__ __half g_fh [(size_t)N_TOK * DFF];
__device__ float g_x1[N_TOK * DMODEL];
__device__ float g_b3[QKV_M];

// ---------------- helpers ----------------
__device__ __forceinline__ uint32_t smem_u32(const void* p) {
    uint32_t a;
    asm("{ .reg .u64 t; cvta.to.shared.u64 t, %1; cvt.u32.u64 %0, t; }" : "=r"(a) : "l"(p));
    return a;
}
__device__ __forceinline__ void cp16(uint32_t s, const void* g) {
    asm volatile("cp.async.cg.shared.global [%0], [%1], 16;" :: "r"(s), "l"(g));
}
__device__ __forceinline__ void cp_commit() { asm volatile("cp.async.commit_group;"); }
__device__ __forceinline__ void cp_wait4()  { asm volatile("cp.async.wait_group 4;"); }
__device__ __forceinline__ void cp_wait1()  { asm volatile("cp.async.wait_group 1;"); }
__device__ __forceinline__ void cp_wait0()  { asm volatile("cp.async.wait_group 0;"); }
__device__ __forceinline__ void ldsm4(uint32_t* r, uint32_t addr) {
    asm volatile("ldmatrix.sync.aligned.m8n8.x4.shared.b16 {%0,%1,%2,%3}, [%4];"
                 : "=r"(r[0]), "=r"(r[1]), "=r"(r[2]), "=r"(r[3]) : "r"(addr));
}
__device__ __forceinline__ void ldsm4t(uint32_t* r, uint32_t addr) {
    asm volatile("ldmatrix.sync.aligned.m8n8.x4.trans.shared.b16 {%0,%1,%2,%3}, [%4];"
                 : "=r"(r[0]), "=r"(r[1]), "=r"(r[2]), "=r"(r[3]) : "r"(addr));
}
__device__ __forceinline__ void mma_f16(float* c, const uint32_t* a, uint32_t b0, uint32_t b1) {
    asm volatile("mma.sync.aligned.m16n8k16.row.col.f32.f16.f16.f32 "
                 "{%0,%1,%2,%3}, {%4,%5,%6,%7}, {%8,%9}, {%0,%1,%2,%3};"
                 : "+f"(c[0]), "+f"(c[1]), "+f"(c[2]), "+f"(c[3])
                 : "r"(a[0]), "r"(a[1]), "r"(a[2]), "r"(a[3]), "r"(b0), "r"(b1));
}
__device__ __forceinline__ uint32_t f2h2(float a, float b) {
    __half2 h = __floats2half2_rn(a, b);
    return *reinterpret_cast<uint32_t*>(&h);
}
// 2^y on the FMA pipe (y <= 0; clamped below -125). rel err ~1e-7.
__device__ __forceinline__ float fexp2(float y) {
    y = fmaxf(y, -125.f);
    float r = y + 12582912.f;
    float f = y - (r - 12582912.f);
    int n = __float_as_int(r) - 0x4B400000;
    float p = 0.0013333558f;
    p = fmaf(p, f, 0.0096181291f);
    p = fmaf(p, f, 0.055504109f);
    p = fmaf(p, f, 0.24022651f);
    p = fmaf(p, f, 0.69314718f);
    p = fmaf(p, f, 1.0f);
    return p * __int_as_float((n + 127) << 23);
}

// ---------------- LayerNorm (fp16 single-plane output) ----------------
__global__ void __launch_bounds__(256) ln_kernel(const float* __restrict__ x,
                                                 const float* __restrict__ gamma,
                                                 const float* __restrict__ beta,
                                                 __half* __restrict__ ohi) {
    int row = blockIdx.x;
    int t = threadIdx.x;
    const float4 v = reinterpret_cast<const float4*>(x + (size_t)row * DMODEL)[t];
    float s  = v.x + v.y + v.z + v.w;
    float sq = v.x * v.x + v.y * v.y + v.z * v.z + v.w * v.w;
    #pragma unroll
    for (int o = 16; o; o >>= 1) {
        s  += __shfl_xor_sync(0xFFFFFFFFu, s,  o);
        sq += __shfl_xor_sync(0xFFFFFFFFu, sq, o);
    }
    __shared__ float ss[8], ssq[8];
    __shared__ float s_mean, s_rstd;
    int wid = t >> 5, lane = t & 31;
    if (lane == 0) { ss[wid] = s; ssq[wid] = sq; }
    __syncthreads();
    if (t == 0) {
        float ts = 0.f, tq = 0.f;
        #pragma unroll
        for (int i = 0; i < 8; i++) { ts += ss[i]; tq += ssq[i]; }
        float mean = ts * (1.0f / DMODEL);
        float var  = tq * (1.0f / DMODEL) - mean * mean;
        s_mean = mean;
        s_rstd = rsqrtf(var + 1e-5f);
    }
    __syncthreads();
    float mean = s_mean, rstd = s_rstd;
    float4 g4 = reinterpret_cast<const float4*>(gamma)[t];
    float4 b4 = reinterpret_cast<const float4*>(beta)[t];
    float o0 = (v.x - mean) * rstd * g4.x + b4.x;
    float o1 = (v.y - mean) * rstd * g4.y + b4.y;
    float o2 = (v.z - mean) * rstd * g4.z + b4.z;
    float o3 = (v.w - mean) * rstd * g4.w + b4.w;
    size_t idx = (size_t)row * DMODEL + t * 4;
    *reinterpret_cast<__half2*>(ohi + idx)     = __floats2half2_rn(o0, o1);
    *reinterpret_cast<__half2*>(ohi + idx + 2) = __floats2half2_rn(o2, o3);
}

// ---------------- all-weights transpose + fp16 convert (single launch) ----------------
__global__ void __launch_bounds__(256) wsplit_all(const float* __restrict__ Wq,
                                                  const float* __restrict__ Wk,
                                                  const float* __restrict__ Wv,
                                                  const float* __restrict__ Wo,
                                                  const float* __restrict__ W1,
                                                  const float* __restrict__ W2,
                                                  __half* __restrict__ out) {
    __shared__ float tile[32][33];
    int id = blockIdx.x;
    const float* W;
    int K, M, n0, k0;
    uint32_t base;
    if (id < 4096) {
        int wsel = id >> 10, local = id & 1023;
        K = M = 1024;
        n0 = (local & 31) * 32; k0 = (local >> 5) * 32;
        W = (wsel == 0) ? Wq : (wsel == 1) ? Wk : (wsel == 2) ? Wv : Wo;
        base = (uint32_t)wsel << 20;
    } else if (id < 8192) {
        int local = id - 4096;
        K = 1024; M = 4096;
        n0 = (local & 127) * 32; k0 = (local >> 7) * 32;
        W = W1; base = W1O;
    } else {
        int local = id - 8192;
        K = 4096; M = 1024;
        n0 = (local & 31) * 32; k0 = (local >> 5) * 32;
        W = W2; base = W2O;
    }
    int tx = threadIdx.x & 31, ty = threadIdx.x >> 5;
    #pragma unroll
    for (int i = 0; i < 4; i++)
        tile[ty + 8 * i][tx] = W[(size_t)(k0 + ty + 8 * i) * M + n0 + tx];
    __syncthreads();
    #pragma unroll
    for (int i = 0; i < 4; i++) {
        float x = tile[tx][ty + 8 * i];
        out[(size_t)base + (size_t)(n0 + ty + 8 * i) * K + k0 + tx] = __float2half_rn(x);
    }
}

__global__ void biascat_kernel(const float* bq, const float* bk, const float* bv, float* out) {
    int i = blockIdx.x * 256 + threadIdx.x;
    float v = (i < 1024) ? bq[i] : (i < 2048) ? bk[i - 1024] : bv[i - 2048];
    out[i] = v;
}

#define GEMM_SMEM (6 * 16384)

// ---------------- QKV GEMM: 4 warps, 64x64 warp tiles ----------------
__global__ void __launch_bounds__(128, 2) gemm_qkv4(const __half* __restrict__ Ah,
                                                    const __half* __restrict__ Bh,
                                                    const float* __restrict__ bias,
                                                    __half* __restrict__ Chi,
                                                    __half* __restrict__ Clo,
                                                    int K, int M) {
    extern __shared__ char smc[];
    uint32_t sb = smem_u32(smc);
    int t = threadIdx.x, lane = t & 31, wid = t >> 5;
    int wr = wid & 1, wc = wid >> 1;
    int m0 = blockIdx.x * 128;
    size_t row0 = (size_t)blockIdx.y * 128;

    int lr = t >> 2, lq = t & 3;
    uint32_t sOl[4];
    #pragma unroll
    for (int i = 0; i < 4; i++) {
        int row = lr + i * 32;
        sOl[i] = (uint32_t)(row * 64 + ((lq ^ ((row >> 1) & 3)) << 4));
    }
    const __half* gA = Ah + (row0 + lr) * (size_t)K + lq * 8;
    const __half* gB = Bh + (size_t)(m0 + lr) * K + lq * 8;

    int g = lane >> 3, l7 = lane & 7;
    uint32_t aRO[4], aSW[4];
    #pragma unroll
    for (int mt = 0; mt < 4; mt++) {
        int arow = wr * 64 + mt * 16 + l7 + ((g & 1) << 3);
        aRO[mt] = (uint32_t)(arow * 64);
        aSW[mt] = (uint32_t)((arow >> 1) & 3);
    }
    uint32_t aKH = (uint32_t)(g >> 1);
    int brow_base = wc * 64 + ((g >> 1) << 3) + l7;
    uint32_t bKH = (uint32_t)(g & 1);

    float acc[4][8][4];
    #pragma unroll
    for (int i = 0; i < 4; i++)
        #pragma unroll
        for (int j = 0; j < 8; j++)
            #pragma unroll
            for (int u = 0; u < 4; u++) acc[i][j][u] = 0.f;

    int NC = K >> 5;
    #pragma unroll
    for (int pk = 0; pk < 5; pk++) {
        uint32_t bb = sb + (uint32_t)pk * 16384u;
        int ko = pk * 32;
        #pragma unroll
        for (int i = 0; i < 4; i++) {
            cp16(bb + sOl[i],        gA + (size_t)i * 32 * K + ko);
            cp16(bb + 8192 + sOl[i], gB + (size_t)i * 32 * K + ko);
        }
        cp_commit();
    }

    int stage = 0, nstage = 5;
    for (int kt = 0; kt < NC; kt++) {
        cp_wait4();
        __syncthreads();
        if (kt + 5 < NC) {
            uint32_t bb = sb + (uint32_t)nstage * 16384u;
            int ko = (kt + 5) * 32;
            #pragma unroll
            for (int i = 0; i < 4; i++) {
                cp16(bb + sOl[i],        gA + (size_t)i * 32 * K + ko);
                cp16(bb + 8192 + sOl[i], gB + (size_t)i * 32 * K + ko);
            }
        }
        cp_commit();

        uint32_t bb = sb + (uint32_t)stage * 16384u;
        #pragma unroll
        for (int ks = 0; ks < 2; ks++) {
            uint32_t ac = (uint32_t)(ks * 2) + aKH;
            uint32_t af[4][4];
            #pragma unroll
            for (int mt = 0; mt < 4; mt++)
                ldsm4(af[mt], bb + aRO[mt] + ((ac ^ aSW[mt]) << 4));
            #pragma unroll
            for (int nh = 0; nh < 4; nh++) {
                int brow = brow_base + nh * 16;
                uint32_t bu = (uint32_t)(ks * 2) + bKH;
                uint32_t boff = (uint32_t)(brow * 64) + ((bu ^ (uint32_t)((brow >> 1) & 3)) << 4);
                uint32_t bh[4];
                ldsm4(bh, bb + 8192 + boff);
                #pragma unroll
                for (int mt = 0; mt < 4; mt++)
                    #pragma unroll
                    for (int s = 0; s < 2; s++)
                        mma_f16(acc[mt][nh * 2 + s], af[mt], bh[s * 2], bh[s * 2 + 1]);
            }
        }
        stage = (stage == 5) ? 0 : stage + 1;
        nstage = (nstage == 5) ? 0 : nstage + 1;
    }

    #pragma unroll
    for (int mt = 0; mt < 4; mt++) {
        size_t rbase = row0 + wr * 64 + mt * 16 + (lane >> 2);
        #pragma unroll
        for (int nt = 0; nt < 8; nt++) {
            int col = m0 + wc * 64 + nt * 8 + (lane & 3) * 2;
            float b0 = bias[col], b1 = bias[col + 1];
            #pragma unroll
            for (int half = 0; half < 2; half++) {
                size_t row = rbase + half * 8;
                float v0 = acc[mt][nt][half * 2 + 0] + b0;
                float v1 = acc[mt][nt][half * 2 + 1] + b1;
                __half2 hp = __floats2half2_rn(v0, v1);
                __half2 lp = __floats2half2_rn(v0 - __low2float(hp),
                                               v1 - __high2float(hp));
                *reinterpret_cast<__half2*>(Chi + row * M + col) = hp;
                *reinterpret_cast<__half2*>(Clo + row * M + col) = lp;
            }
        }
    }
}

// ---------------- 8-warp GEMM: 32x64 tiles (Wo / FFN1 / FFN2) ----------------
// SPLIT: 0 = fp32 out (+res), 2 = fp16 hi plane only
template<int GELU, int RES, int SPLIT>
__global__ void __launch_bounds__(256, 2) gemm_mma(const __half* __restrict__ Ah,
                                                   const __half* __restrict__ Bh,
                                                   const float* __restrict__ bias,
                                                   const float* __restrict__ res,
                                                   float* __restrict__ C,
                                                   __half* __restrict__ Chi,
                                                   int K, int M) {
    extern __shared__ char smc[];
    uint32_t sb = smem_u32(smc);
    int t = threadIdx.x, lane = t & 31, wid = t >> 5;
    int wr = wid & 3, wc = wid >> 2;
    int m0 = blockIdx.x * 128;
    size_t row0 = (size_t)blockIdx.y * 128;

    int r0 = t >> 2, cq = t & 3;
    int r1 = r0 + 64;
    uint32_t sO0 = (uint32_t)(r0 * 64 + ((cq ^ ((r0 >> 1) & 3)) << 4));
    uint32_t sO1 = (uint32_t)(r1 * 64 + ((cq ^ ((r1 >> 1) & 3)) << 4));
    const __half* gA0 = Ah + (row0 + r0) * (size_t)K + cq * 8;
    const __half* gA1 = Ah + (row0 + r1) * (size_t)K + cq * 8;
    const __half* gB0 = Bh + (size_t)(m0 + r0) * K + cq * 8;
    const __half* gB1 = Bh + (size_t)(m0 + r1) * K + cq * 8;

    int g = lane >> 3, l7 = lane & 7;
    int arow0 = wr * 32 + l7 + ((g & 1) << 3);
    int arow1 = arow0 + 16;
    uint32_t aRO0 = (uint32_t)(arow0 * 64), aSW0 = (uint32_t)((arow0 >> 1) & 3);
    uint32_t aRO1 = (uint32_t)(arow1 * 64), aSW1 = (uint32_t)((arow1 >> 1) & 3);
    uint32_t aKH = (uint32_t)(g >> 1);
    int brow_base = wc * 64 + ((g >> 1) << 3) + l7;
    uint32_t bKH = (uint32_t)(g & 1);

    float acc[2][8][4];
    #pragma unroll
    for (int i = 0; i < 2; i++)
        #pragma unroll
        for (int j = 0; j < 8; j++)
            #pragma unroll
            for (int u = 0; u < 4; u++) acc[i][j][u] = 0.f;

    int NC = K >> 5;
    #pragma unroll
    for (int pk = 0; pk < 5; pk++) {
        uint32_t bb = sb + (uint32_t)pk * 16384u;
        int ko = pk * 32;
        cp16(bb + sO0,        gA0 + ko); cp16(bb + sO1,        gA1 + ko);
        cp16(bb + 8192 + sO0, gB0 + ko); cp16(bb + 8192 + sO1, gB1 + ko);
        cp_commit();
    }

    int stage = 0, nstage = 5;
    for (int kt = 0; kt < NC; kt++) {
        cp_wait4();
        __syncthreads();
        if (kt + 5 < NC) {
            uint32_t bb = sb + (uint32_t)nstage * 16384u;
            int ko = (kt + 5) * 32;
            cp16(bb + sO0,        gA0 + ko); cp16(bb + sO1,        gA1 + ko);
            cp16(bb + 8192 + sO0, gB0 + ko); cp16(bb + 8192 + sO1, gB1 + ko);
        }
        cp_commit();

        uint32_t bb = sb + (uint32_t)stage * 16384u;
        #pragma unroll
        for (int ks = 0; ks < 2; ks++) {
            uint32_t ac = (uint32_t)(ks * 2) + aKH;
            uint32_t ah0[4], ah1[4];
            ldsm4(ah0, bb + aRO0 + ((ac ^ aSW0) << 4));
            ldsm4(ah1, bb + aRO1 + ((ac ^ aSW1) << 4));
            #pragma unroll
            for (int nh = 0; nh < 4; nh++) {
                int brow = brow_base + nh * 16;
                uint32_t bRO = (uint32_t)(brow * 64), bSW = (uint32_t)((brow >> 1) & 3);
                uint32_t bc = (uint32_t)(ks * 2) + bKH;
                uint32_t boff = bRO + ((bc ^ bSW) << 4);
                uint32_t bh[4];
                ldsm4(bh, bb + 8192 + boff);
                #pragma unroll
                for (int s = 0; s < 2; s++) {
                    mma_f16(acc[0][nh * 2 + s], ah0, bh[s * 2], bh[s * 2 + 1]);
                    mma_f16(acc[1][nh * 2 + s], ah1, bh[s * 2], bh[s * 2 + 1]);
                }
            }
        }
        stage = (stage == 5) ? 0 : stage + 1;
        nstage = (nstage == 5) ? 0 : nstage + 1;
    }

    #pragma unroll
    for (int mt = 0; mt < 2; mt++) {
        size_t rbase = row0 + wr * 32 + mt * 16 + (lane >> 2);
        #pragma unroll
        for (int nt = 0; nt < 8; nt++) {
            int col = m0 + wc * 64 + nt * 8 + (lane & 3) * 2;
            float b0 = bias[col], b1 = bias[col + 1];
            #pragma unroll
            for (int half = 0; half < 2; half++) {
                size_t row = rbase + half * 8;
                float v0 = acc[mt][nt][half * 2 + 0] + b0;
                float v1 = acc[mt][nt][half * 2 + 1] + b1;
                if (GELU) { v0 = v0 * normcdff(v0); v1 = v1 * normcdff(v1); }
                if (RES) {
                    float2 r2 = *reinterpret_cast<const float2*>(res + row * M + col);
                    v0 += r2.x; v1 += r2.y;
                }
                if (SPLIT == 2) {
                    *reinterpret_cast<__half2*>(Chi + row * M + col) = __floats2half2_rn(v0, v1);
                } else {
                    *reinterpret_cast<float2*>(C + row * M + col) = make_float2(v0, v1);
                }
            }
        }
    }
}

// ---------------- mma.sync causal flash attention: 8 warps x 16 q-rows, 2 CTAs/SM -----
// smem: Qh [128][64] @0 (16KB), Ql @16384 (16KB); KV stages @32768: 2 x (Kh 8KB + Vh 8KB).
#define ATT_SMEM 65536
#define SCALE_L2E 0.18033688f   // 0.125 * log2(e)

__global__ void __launch_bounds__(256, 2) attn_mma(const __half* __restrict__ qkvh,
                                                   const __half* __restrict__ qkvl,
                                                   __half* __restrict__ ohi) {
    extern __shared__ char smc[];
    uint32_t sb = smem_u32(smc);
    int t = threadIdx.x, lane = t & 31, w = t >> 5;
    int g = lane >> 3, l7 = lane & 7;
    int bh = blockIdx.y;
    int b = bh >> 4, h = bh & 15;
    int qt = (SEQ / 128 - 1) - blockIdx.x;
    int qb = qt * 128;
    size_t tok0 = (size_t)(b * SEQ + qb);

    {
        #pragma unroll
        for (int i = 0; i < 8; i++) {
            int c = t + i * 256;
            int plane = c >> 10, rem = c & 1023;
            int row = rem >> 3, u = rem & 7;
            uint32_t so = (uint32_t)(plane * 16384 + row * 128 + ((u ^ (row & 7)) << 4));
            const __half* gp = (plane ? qkvl : qkvh) + (tok0 + row) * QKV_M + h * 64 + u * 8;
            cp16(sb + so, gp);
        }
        size_t ktok = (size_t)(b * SEQ);
        #pragma unroll
        for (int i = 0; i < 4; i++) {
            int c = t + i * 256;
            int plane = c >> 9, rem = c & 511;   // 0=K, 1=V
            int row = rem >> 3, u = rem & 7;
            uint32_t so = (uint32_t)(32768 + plane * 8192 + row * 128 + ((u ^ (row & 7)) << 4));
            const __half* gp = qkvh + (ktok + row) * QKV_M + 1024 + plane * 1024 + h * 64 + u * 8;
            cp16(sb + so, gp);
        }
        cp_commit();
    }

    uint32_t qah[4][4], qal[4][4];
    float m0 = -1e30f, m1 = -1e30f, l0 = 0.f, l1 = 0.f;
    float o[8][4];
    #pragma unroll
    for (int j = 0; j < 8; j++)
        #pragma unroll
        for (int u = 0; u < 4; u++) o[j][u] = 0.f;

    int q0g = qb + w * 16 + (lane >> 2);
    int q1g = q0g + 8;

    int ntiles = 2 * qt + 2;
    for (int kt = 0; kt < ntiles; kt++) {
        int k0 = kt * 64;
        if (kt + 1 < ntiles) {
            uint32_t bufb = 32768u + (uint32_t)((kt + 1) & 1) * 16384u;
            size_t ktok = (size_t)(b * SEQ + (kt + 1) * 64);
            #pragma unroll
            for (int i = 0; i < 4; i++) {
                int c = t + i * 256;
                int plane = c >> 9, rem = c & 511;
                int row = rem >> 3, u = rem & 7;
                uint32_t so = bufb + (uint32_t)(plane * 8192 + row * 128 + ((u ^ (row & 7)) << 4));
                const __half* gp = qkvh + (ktok + row) * QKV_M + 1024 + plane * 1024 + h * 64 + u * 8;
                cp16(sb + so, gp);
            }
            cp_commit();
            cp_wait1();
        } else {
            cp_wait0();
        }
        __syncthreads();

        if (kt == 0) {
            int arow = w * 16 + (lane & 15);
            uint32_t aro = (uint32_t)(arow * 128);
            uint32_t asw = (uint32_t)(arow & 7);
            #pragma unroll
            for (int ks = 0; ks < 4; ks++) {
                uint32_t u = (uint32_t)(ks * 2) + (uint32_t)(lane >> 4);
                uint32_t off = aro + ((u ^ asw) << 4);
                ldsm4(qah[ks], sb + off);
                ldsm4(qal[ks], sb + 16384 + off);
            }
        }

        uint32_t kvb = sb + 32768u + (uint32_t)(kt & 1) * 16384u;

        float s[8][4];
        #pragma unroll
        for (int j = 0; j < 8; j++)
            #pragma unroll
            for (int u = 0; u < 4; u++) s[j][u] = 0.f;

        #pragma unroll
        for (int nh = 0; nh < 4; nh++) {
            int brow = nh * 16 + ((g >> 1) << 3) + l7;
            uint32_t bro = (uint32_t)(brow * 128);
            uint32_t bsw = (uint32_t)(brow & 7);
            #pragma unroll
            for (int ks = 0; ks < 4; ks++) {
                uint32_t u = (uint32_t)(ks * 2) + (uint32_t)(g & 1);
                uint32_t off = bro + ((u ^ bsw) << 4);
                uint32_t bhf[4];
                ldsm4(bhf, kvb + off);
                float* c0 = s[nh * 2];
                float* c1 = s[nh * 2 + 1];
                mma_f16(c0, qah[ks], bhf[0], bhf[1]);
                mma_f16(c0, qal[ks], bhf[0], bhf[1]);
                mma_f16(c1, qah[ks], bhf[2], bhf[3]);
                mma_f16(c1, qal[ks], bhf[2], bhf[3]);
            }
        }

        bool diag = (kt >= 2 * qt);
        float mx0 = -1e30f, mx1 = -1e30f;
        #pragma unroll
        for (int j = 0; j < 8; j++) {
            int kb = k0 + j * 8 + ((lane & 3) << 1);
            float y0 = s[j][0] * SCALE_L2E;
            float y1 = s[j][1] * SCALE_L2E;
            float y2 = s[j][2] * SCALE_L2E;
            float y3 = s[j][3] * SCALE_L2E;
            if (diag) {
                if (kb     > q0g) y0 = -1e30f;
                if (kb + 1 > q0g) y1 = -1e30f;
                if (kb     > q1g) y2 = -1e30f;
                if (kb + 1 > q1g) y3 = -1e30f;
            }
            s[j][0] = y0; s[j][1] = y1; s[j][2] = y2; s[j][3] = y3;
            mx0 = fmaxf(mx0, fmaxf(y0, y1));
            mx1 = fmaxf(mx1, fmaxf(y2, y3));
        }
        mx0 = fmaxf(mx0, __shfl_xor_sync(0xFFFFFFFFu, mx0, 1));
        mx0 = fmaxf(mx0, __shfl_xor_sync(0xFFFFFFFFu, mx0, 2));
        mx1 = fmaxf(mx1, __shfl_xor_sync(0xFFFFFFFFu, mx1, 1));
        mx1 = fmaxf(mx1, __shfl_xor_sync(0xFFFFFFFFu, mx1, 2));

        float m0n = fmaxf(m0, mx0), m1n = fmaxf(m1, mx1);
        float corr0 = fexp2(m0 - m0n), corr1 = fexp2(m1 - m1n);
        m0 = m0n; m1 = m1n;

        float rs0 = 0.f, rs1 = 0.f;
        #pragma unroll
        for (int j = 0; j < 8; j++) {
            float p0 = fexp2(s[j][0] - m0);
            float p1 = fexp2(s[j][1] - m0);
            float p2 = fexp2(s[j][2] - m1);
            float p3 = fexp2(s[j][3] - m1);
            s[j][0] = p0; s[j][1] = p1; s[j][2] = p2; s[j][3] = p3;
            rs0 += p0 + p1; rs1 += p2 + p3;
        }
        rs0 += __shfl_xor_sync(0xFFFFFFFFu, rs0, 1);
        rs0 += __shfl_xor_sync(0xFFFFFFFFu, rs0, 2);
        rs1 += __shfl_xor_sync(0xFFFFFFFFu, rs1, 1);
        rs1 += __shfl_xor_sync(0xFFFFFFFFu, rs1, 2);
        l0 = l0 * corr0 + rs0;
        l1 = l1 * corr1 + rs1;
        #pragma unroll
        for (int j = 0; j < 8; j++) {
            o[j][0] *= corr0; o[j][1] *= corr0;
            o[j][2] *= corr1; o[j][3] *= corr1;
        }

        #pragma unroll
        for (int ks2 = 0; ks2 < 4; ks2++) {
            int j0 = ks2 * 2, j1 = j0 + 1;
            uint32_t aPh[4];
            aPh[0] = f2h2(s[j0][0], s[j0][1]);
            aPh[1] = f2h2(s[j0][2], s[j0][3]);
            aPh[2] = f2h2(s[j1][0], s[j1][1]);
            aPh[3] = f2h2(s[j1][2], s[j1][3]);

            int vrow = ks2 * 16 + ((g & 1) << 3) + l7;
            uint32_t vro = (uint32_t)(vrow * 128);
            uint32_t vsw = (uint32_t)(vrow & 7);
            #pragma unroll
            for (int dh = 0; dh < 4; dh++) {
                uint32_t u = (uint32_t)(dh * 2) + (uint32_t)(g >> 1);
                uint32_t off = vro + ((u ^ vsw) << 4);
                uint32_t vhf[4];
                ldsm4t(vhf, kvb + 8192 + off);
                mma_f16(o[dh * 2],     aPh, vhf[0], vhf[1]);
                mma_f16(o[dh * 2 + 1], aPh, vhf[2], vhf[3]);
            }
        }
        __syncthreads();
    }

    float inv0 = 1.0f / l0, inv1 = 1.0f / l1;
    size_t r0o = ((size_t)(b * SEQ) + q0g) * DMODEL + h * 64;
    size_t r1o = ((size_t)(b * SEQ) + q1g) * DMODEL + h * 64;
    #pragma unroll
    for (int j = 0; j < 8; j++) {
        int col = j * 8 + (lane & 3) * 2;
        *reinterpret_cast<__half2*>(ohi + r0o + col) =
            __floats2half2_rn(o[j][0] * inv0, o[j][1] * inv0);
        *reinterpret_cast<__half2*>(ohi + r1o + col) =
            __floats2half2_rn(o[j][2] * inv1, o[j][3] * inv1);
    }
}

// ---------------- launch ----------------
extern "C" void kernel_launch(void* const* d_in, const int* in_sizes, int n_in,
                              void* d_out, int out_size) {
    const float* x    = (const float*)d_in[0];
    const float* ln1g = (const float*)d_in[1];
    const float* ln1b = (const float*)d_in[2];
    const float* Wq   = (const float*)d_in[3];
    const float* bq   = (const float*)d_in[4];
    const float* Wk   = (const float*)d_in[5];
    const float* bk   = (const float*)d_in[6];
    const float* Wv   = (const float*)d_in[7];
    const float* bv   = (const float*)d_in[8];
    const float* Wo   = (const float*)d_in[9];
    const float* bo   = (const float*)d_in[10];
    const float* ln2g = (const float*)d_in[11];
    const float* ln2b = (const float*)d_in[12];
    const float* W1   = (const float*)d_in[13];
    const float* b1   = (const float*)d_in[14];
    const float* W2   = (const float*)d_in[15];
    const float* b2   = (const float*)d_in[16];
    float* out = (float*)d_out;

    __half *w, *hh, *qkvh, *qkvl, *oh, *fh;
    float *x1, *b3;
    cudaGetSymbolAddress((void**)&w,    g_w);
    cudaGetSymbolAddress((void**)&hh,   g_hh);
    cudaGetSymbolAddress((void**)&qkvh, g_qkvh);
    cudaGetSymbolAddress((void**)&qkvl, g_qkvl);
    cudaGetSymbolAddress((void**)&oh,   g_oh);
    cudaGetSymbolAddress((void**)&fh,   g_fh);
    cudaGetSymbolAddress((void**)&x1,   g_x1);
    cudaGetSymbolAddress((void**)&b3,   g_b3);

    static int attr_set = 0;
    if (!attr_set) {
        cudaFuncSetAttribute(attn_mma, cudaFuncAttributeMaxDynamicSharedMemorySize, ATT_SMEM);
        cudaFuncSetAttribute(gemm_qkv4, cudaFuncAttributeMaxDynamicSharedMemorySize, GEMM_SMEM);
        cudaFuncSetAttribute(gemm_mma<0, 1, 0>, cudaFuncAttributeMaxDynamicSharedMemorySize, GEMM_SMEM);
        cudaFuncSetAttribute(gemm_mma<1, 0, 2>, cudaFuncAttributeMaxDynamicSharedMemorySize, GEMM_SMEM);
        attr_set = 1;
    }

    wsplit_all<<<12288, 256>>>(Wq, Wk, Wv, Wo, W1, W2, w);
    biascat_kernel<<<12, 256>>>(bq, bk, bv, b3);

    // --- attention sublayer ---
    ln_kernel<<<N_TOK, 256>>>(x, ln1g, ln1b, hh);
    gemm_qkv4<<<dim3(QKV_M / 128, 32), 128, GEMM_SMEM>>>(
        hh, w + WQO, b3, qkvh, qkvl, DMODEL, QKV_M);
    attn_mma<<<dim3(SEQ / 128, NHEAD * BATCH), 256, ATT_SMEM>>>(qkvh, qkvl, oh);
    gemm_mma<0, 1, 0><<<dim3(8, 32), 256, GEMM_SMEM>>>(
        oh, w + WOO, bo, x, x1, nullptr, DMODEL, DMODEL);

    // --- FFN sublayer ---
    ln_kernel<<<N_TOK, 256>>>(x1, ln2g, ln2b, hh);
    gemm_mma<1, 0, 2><<<dim3(32, 32), 256, GEMM_SMEM>>>(
        hh, w + W1O, b1, nullptr, nullptr, fh, DMODEL, DFF);
    gemm_mma<0, 1, 0><<<dim3(8, 32), 256, GEMM_SMEM>>>(
        fh, w + W2O, b2, x1, out, nullptr, DFF, DMODEL);
}

// round 17
// speedup vs baseline: 1.0922x; 1.0731x over previous
#include <cuda_runtime.h>
#include <cuda_fp16.h>
#include <math.h>
#include <stdint.h>

#define N_TOK   4096     // B * S
#define DMODEL  1024
#define DFF     4096
#define NHEAD   16
#define DK      64
#define SEQ     2048
#define BATCH   2
#define QKV_M   3072

// ---------------- scratch (static device globals; no allocation) ----------------
#define WQO 0
#define WKO (1u << 20)
#define WVO (2u << 20)
#define WOO (3u << 20)
#define W1O (4u << 20)
#define W2O (8u << 20)
__device__ __half g_w  [12u << 20];                 // weights: fp16, [outfeat][K]
__device__ __half g_hh [N_TOK * DMODEL];            // LN out (single plane)
__device__ __half g_qkvh[(size_t)N_TOK * QKV_M];
__device__ __half g_oh [N_TOK * DMODEL];
__device__ __half g_fh [(size_t)N_TOK * DFF];
__device__ float g_x1[N_TOK * DMODEL];
__device__ float g_b3[QKV_M];

// ---------------- helpers ----------------
__device__ __forceinline__ uint32_t smem_u32(const void* p) {
    uint32_t a;
    asm("{ .reg .u64 t; cvta.to.shared.u64 t, %1; cvt.u32.u64 %0, t; }" : "=r"(a) : "l"(p));
    return a;
}
__device__ __forceinline__ void cp16(uint32_t s, const void* g) {
    asm volatile("cp.async.cg.shared.global [%0], [%1], 16;" :: "r"(s), "l"(g));
}
__device__ __forceinline__ void cp_commit() { asm volatile("cp.async.commit_group;"); }
__device__ __forceinline__ void cp_wait4()  { asm volatile("cp.async.wait_group 4;"); }
__device__ __forceinline__ void cp_wait1()  { asm volatile("cp.async.wait_group 1;"); }
__device__ __forceinline__ void cp_wait0()  { asm volatile("cp.async.wait_group 0;"); }
__device__ __forceinline__ void ldsm4(uint32_t* r, uint32_t addr) {
    asm volatile("ldmatrix.sync.aligned.m8n8.x4.shared.b16 {%0,%1,%2,%3}, [%4];"
                 : "=r"(r[0]), "=r"(r[1]), "=r"(r[2]), "=r"(r[3]) : "r"(addr));
}
__device__ __forceinline__ void ldsm4t(uint32_t* r, uint32_t addr) {
    asm volatile("ldmatrix.sync.aligned.m8n8.x4.trans.shared.b16 {%0,%1,%2,%3}, [%4];"
                 : "=r"(r[0]), "=r"(r[1]), "=r"(r[2]), "=r"(r[3]) : "r"(addr));
}
__device__ __forceinline__ void mma_f16(float* c, const uint32_t* a, uint32_t b0, uint32_t b1) {
    asm volatile("mma.sync.aligned.m16n8k16.row.col.f32.f16.f16.f32 "
                 "{%0,%1,%2,%3}, {%4,%5,%6,%7}, {%8,%9}, {%0,%1,%2,%3};"
                 : "+f"(c[0]), "+f"(c[1]), "+f"(c[2]), "+f"(c[3])
                 : "r"(a[0]), "r"(a[1]), "r"(a[2]), "r"(a[3]), "r"(b0), "r"(b1));
}
__device__ __forceinline__ uint32_t f2h2(float a, float b) {
    __half2 h = __floats2half2_rn(a, b);
    return *reinterpret_cast<uint32_t*>(&h);
}
// 2^y on the FMA pipe (y <= 0; clamped below -125). rel err ~1e-7.
__device__ __forceinline__ float fexp2(float y) {
    y = fmaxf(y, -125.f);
    float r = y + 12582912.f;
    float f = y - (r - 12582912.f);
    int n = __float_as_int(r) - 0x4B400000;
    float p = 0.0013333558f;
    p = fmaf(p, f, 0.0096181291f);
    p = fmaf(p, f, 0.055504109f);
    p = fmaf(p, f, 0.24022651f);
    p = fmaf(p, f, 0.69314718f);
    p = fmaf(p, f, 1.0f);
    return p * __int_as_float((n + 127) << 23);
}

// ---------------- LayerNorm (fp16 single-plane output) ----------------
__global__ void __launch_bounds__(256) ln_kernel(const float* __restrict__ x,
                                                 const float* __restrict__ gamma,
                                                 const float* __restrict__ beta,
                                                 __half* __restrict__ ohi) {
    int row = blockIdx.x;
    int t = threadIdx.x;
    const float4 v = reinterpret_cast<const float4*>(x + (size_t)row * DMODEL)[t];
    float s  = v.x + v.y + v.z + v.w;
    float sq = v.x * v.x + v.y * v.y + v.z * v.z + v.w * v.w;
    #pragma unroll
    for (int o = 16; o; o >>= 1) {
        s  += __shfl_xor_sync(0xFFFFFFFFu, s,  o);
        sq += __shfl_xor_sync(0xFFFFFFFFu, sq, o);
    }
    __shared__ float ss[8], ssq[8];
    __shared__ float s_mean, s_rstd;
    int wid = t >> 5, lane = t & 31;
    if (lane == 0) { ss[wid] = s; ssq[wid] = sq; }
    __syncthreads();
    if (t == 0) {
        float ts = 0.f, tq = 0.f;
        #pragma unroll
        for (int i = 0; i < 8; i++) { ts += ss[i]; tq += ssq[i]; }
        float mean = ts * (1.0f / DMODEL);
        float var  = tq * (1.0f / DMODEL) - mean * mean;
        s_mean = mean;
        s_rstd = rsqrtf(var + 1e-5f);
    }
    __syncthreads();
    float mean = s_mean, rstd = s_rstd;
    float4 g4 = reinterpret_cast<const float4*>(gamma)[t];
    float4 b4 = reinterpret_cast<const float4*>(beta)[t];
    float o0 = (v.x - mean) * rstd * g4.x + b4.x;
    float o1 = (v.y - mean) * rstd * g4.y + b4.y;
    float o2 = (v.z - mean) * rstd * g4.z + b4.z;
    float o3 = (v.w - mean) * rstd * g4.w + b4.w;
    size_t idx = (size_t)row * DMODEL + t * 4;
    *reinterpret_cast<__half2*>(ohi + idx)     = __floats2half2_rn(o0, o1);
    *reinterpret_cast<__half2*>(ohi + idx + 2) = __floats2half2_rn(o2, o3);
}

// ---------------- all-weights transpose + fp16 convert (single launch) ----------------
__global__ void __launch_bounds__(256) wsplit_all(const float* __restrict__ Wq,
                                                  const float* __restrict__ Wk,
                                                  const float* __restrict__ Wv,
                                                  const float* __restrict__ Wo,
                                                  const float* __restrict__ W1,
                                                  const float* __restrict__ W2,
                                                  __half* __restrict__ out) {
    __shared__ float tile[32][33];
    int id = blockIdx.x;
    const float* W;
    int K, M, n0, k0;
    uint32_t base;
    if (id < 4096) {
        int wsel = id >> 10, local = id & 1023;
        K = M = 1024;
        n0 = (local & 31) * 32; k0 = (local >> 5) * 32;
        W = (wsel == 0) ? Wq : (wsel == 1) ? Wk : (wsel == 2) ? Wv : Wo;
        base = (uint32_t)wsel << 20;
    } else if (id < 8192) {
        int local = id - 4096;
        K = 1024; M = 4096;
        n0 = (local & 127) * 32; k0 = (local >> 7) * 32;
        W = W1; base = W1O;
    } else {
        int local = id - 8192;
        K = 4096; M = 1024;
        n0 = (local & 31) * 32; k0 = (local >> 5) * 32;
        W = W2; base = W2O;
    }
    int tx = threadIdx.x & 31, ty = threadIdx.x >> 5;
    #pragma unroll
    for (int i = 0; i < 4; i++)
        tile[ty + 8 * i][tx] = W[(size_t)(k0 + ty + 8 * i) * M + n0 + tx];
    __syncthreads();
    #pragma unroll
    for (int i = 0; i < 4; i++) {
        float x = tile[tx][ty + 8 * i];
        out[(size_t)base + (size_t)(n0 + ty + 8 * i) * K + k0 + tx] = __float2half_rn(x);
    }
}

__global__ void biascat_kernel(const float* bq, const float* bk, const float* bv, float* out) {
    int i = blockIdx.x * 256 + threadIdx.x;
    float v = (i < 1024) ? bq[i] : (i < 2048) ? bk[i - 1024] : bv[i - 2048];
    out[i] = v;
}

#define GEMM_SMEM (6 * 16384)

// ---------------- QKV GEMM: 4 warps, 64x64 warp tiles (fp16 hi plane only) ------------
__global__ void __launch_bounds__(128, 2) gemm_qkv4(const __half* __restrict__ Ah,
                                                    const __half* __restrict__ Bh,
                                                    const float* __restrict__ bias,
                                                    __half* __restrict__ Chi,
                                                    int K, int M) {
    extern __shared__ char smc[];
    uint32_t sb = smem_u32(smc);
    int t = threadIdx.x, lane = t & 31, wid = t >> 5;
    int wr = wid & 1, wc = wid >> 1;
    int m0 = blockIdx.x * 128;
    size_t row0 = (size_t)blockIdx.y * 128;

    int lr = t >> 2, lq = t & 3;
    uint32_t sOl[4];
    #pragma unroll
    for (int i = 0; i < 4; i++) {
        int row = lr + i * 32;
        sOl[i] = (uint32_t)(row * 64 + ((lq ^ ((row >> 1) & 3)) << 4));
    }
    const __half* gA = Ah + (row0 + lr) * (size_t)K + lq * 8;
    const __half* gB = Bh + (size_t)(m0 + lr) * K + lq * 8;

    int g = lane >> 3, l7 = lane & 7;
    uint32_t aRO[4], aSW[4];
    #pragma unroll
    for (int mt = 0; mt < 4; mt++) {
        int arow = wr * 64 + mt * 16 + l7 + ((g & 1) << 3);
        aRO[mt] = (uint32_t)(arow * 64);
        aSW[mt] = (uint32_t)((arow >> 1) & 3);
    }
    uint32_t aKH = (uint32_t)(g >> 1);
    int brow_base = wc * 64 + ((g >> 1) << 3) + l7;
    uint32_t bKH = (uint32_t)(g & 1);

    float acc[4][8][4];
    #pragma unroll
    for (int i = 0; i < 4; i++)
        #pragma unroll
        for (int j = 0; j < 8; j++)
            #pragma unroll
            for (int u = 0; u < 4; u++) acc[i][j][u] = 0.f;

    int NC = K >> 5;
    #pragma unroll
    for (int pk = 0; pk < 5; pk++) {
        uint32_t bb = sb + (uint32_t)pk * 16384u;
        int ko = pk * 32;
        #pragma unroll
        for (int i = 0; i < 4; i++) {
            cp16(bb + sOl[i],        gA + (size_t)i * 32 * K + ko);
            cp16(bb + 8192 + sOl[i], gB + (size_t)i * 32 * K + ko);
        }
        cp_commit();
    }

    int stage = 0, nstage = 5;
    for (int kt = 0; kt < NC; kt++) {
        cp_wait4();
        __syncthreads();
        if (kt + 5 < NC) {
            uint32_t bb = sb + (uint32_t)nstage * 16384u;
            int ko = (kt + 5) * 32;
            #pragma unroll
            for (int i = 0; i < 4; i++) {
                cp16(bb + sOl[i],        gA + (size_t)i * 32 * K + ko);
                cp16(bb + 8192 + sOl[i], gB + (size_t)i * 32 * K + ko);
            }
        }
        cp_commit();

        uint32_t bb = sb + (uint32_t)stage * 16384u;
        #pragma unroll
        for (int ks = 0; ks < 2; ks++) {
            uint32_t ac = (uint32_t)(ks * 2) + aKH;
            uint32_t af[4][4];
            #pragma unroll
            for (int mt = 0; mt < 4; mt++)
                ldsm4(af[mt], bb + aRO[mt] + ((ac ^ aSW[mt]) << 4));
            #pragma unroll
            for (int nh = 0; nh < 4; nh++) {
                int brow = brow_base + nh * 16;
                uint32_t bu = (uint32_t)(ks * 2) + bKH;
                uint32_t boff = (uint32_t)(brow * 64) + ((bu ^ (uint32_t)((brow >> 1) & 3)) << 4);
                uint32_t bh[4];
                ldsm4(bh, bb + 8192 + boff);
                #pragma unroll
                for (int mt = 0; mt < 4; mt++)
                    #pragma unroll
                    for (int s = 0; s < 2; s++)
                        mma_f16(acc[mt][nh * 2 + s], af[mt], bh[s * 2], bh[s * 2 + 1]);
            }
        }
        stage = (stage == 5) ? 0 : stage + 1;
        nstage = (nstage == 5) ? 0 : nstage + 1;
    }

    #pragma unroll
    for (int mt = 0; mt < 4; mt++) {
        size_t rbase = row0 + wr * 64 + mt * 16 + (lane >> 2);
        #pragma unroll
        for (int nt = 0; nt < 8; nt++) {
            int col = m0 + wc * 64 + nt * 8 + (lane & 3) * 2;
            float b0 = bias[col], b1 = bias[col + 1];
            #pragma unroll
            for (int half = 0; half < 2; half++) {
                size_t row = rbase + half * 8;
                float v0 = acc[mt][nt][half * 2 + 0] + b0;
                float v1 = acc[mt][nt][half * 2 + 1] + b1;
                *reinterpret_cast<__half2*>(Chi + row * M + col) = __floats2half2_rn(v0, v1);
            }
        }
    }
}

// ---------------- 8-warp GEMM: 32x64 tiles (Wo / FFN1 / FFN2) ----------------
// SPLIT: 0 = fp32 out (+res), 2 = fp16 hi plane only
template<int GELU, int RES, int SPLIT>
__global__ void __launch_bounds__(256, 2) gemm_mma(const __half* __restrict__ Ah,
                                                   const __half* __restrict__ Bh,
                                                   const float* __restrict__ bias,
                                                   const float* __restrict__ res,
                                                   float* __restrict__ C,
                                                   __half* __restrict__ Chi,
                                                   int K, int M) {
    extern __shared__ char smc[];
    uint32_t sb = smem_u32(smc);
    int t = threadIdx.x, lane = t & 31, wid = t >> 5;
    int wr = wid & 3, wc = wid >> 2;
    int m0 = blockIdx.x * 128;
    size_t row0 = (size_t)blockIdx.y * 128;

    int r0 = t >> 2, cq = t & 3;
    int r1 = r0 + 64;
    uint32_t sO0 = (uint32_t)(r0 * 64 + ((cq ^ ((r0 >> 1) & 3)) << 4));
    uint32_t sO1 = (uint32_t)(r1 * 64 + ((cq ^ ((r1 >> 1) & 3)) << 4));
    const __half* gA0 = Ah + (row0 + r0) * (size_t)K + cq * 8;
    const __half* gA1 = Ah + (row0 + r1) * (size_t)K + cq * 8;
    const __half* gB0 = Bh + (size_t)(m0 + r0) * K + cq * 8;
    const __half* gB1 = Bh + (size_t)(m0 + r1) * K + cq * 8;

    int g = lane >> 3, l7 = lane & 7;
    int arow0 = wr * 32 + l7 + ((g & 1) << 3);
    int arow1 = arow0 + 16;
    uint32_t aRO0 = (uint32_t)(arow0 * 64), aSW0 = (uint32_t)((arow0 >> 1) & 3);
    uint32_t aRO1 = (uint32_t)(arow1 * 64), aSW1 = (uint32_t)((arow1 >> 1) & 3);
    uint32_t aKH = (uint32_t)(g >> 1);
    int brow_base = wc * 64 + ((g >> 1) << 3) + l7;
    uint32_t bKH = (uint32_t)(g & 1);

    float acc[2][8][4];
    #pragma unroll
    for (int i = 0; i < 2; i++)
        #pragma unroll
        for (int j = 0; j < 8; j++)
            #pragma unroll
            for (int u = 0; u < 4; u++) acc[i][j][u] = 0.f;

    int NC = K >> 5;
    #pragma unroll
    for (int pk = 0; pk < 5; pk++) {
        uint32_t bb = sb + (uint32_t)pk * 16384u;
        int ko = pk * 32;
        cp16(bb + sO0,        gA0 + ko); cp16(bb + sO1,        gA1 + ko);
        cp16(bb + 8192 + sO0, gB0 + ko); cp16(bb + 8192 + sO1, gB1 + ko);
        cp_commit();
    }

    int stage = 0, nstage = 5;
    for (int kt = 0; kt < NC; kt++) {
        cp_wait4();
        __syncthreads();
        if (kt + 5 < NC) {
            uint32_t bb = sb + (uint32_t)nstage * 16384u;
            int ko = (kt + 5) * 32;
            cp16(bb + sO0,        gA0 + ko); cp16(bb + sO1,        gA1 + ko);
            cp16(bb + 8192 + sO0, gB0 + ko); cp16(bb + 8192 + sO1, gB1 + ko);
        }
        cp_commit();

        uint32_t bb = sb + (uint32_t)stage * 16384u;
        #pragma unroll
        for (int ks = 0; ks < 2; ks++) {
            uint32_t ac = (uint32_t)(ks * 2) + aKH;
            uint32_t ah0[4], ah1[4];
            ldsm4(ah0, bb + aRO0 + ((ac ^ aSW0) << 4));
            ldsm4(ah1, bb + aRO1 + ((ac ^ aSW1) << 4));
            #pragma unroll
            for (int nh = 0; nh < 4; nh++) {
                int brow = brow_base + nh * 16;
                uint32_t bRO = (uint32_t)(brow * 64), bSW = (uint32_t)((brow >> 1) & 3);
                uint32_t bc = (uint32_t)(ks * 2) + bKH;
                uint32_t boff = bRO + ((bc ^ bSW) << 4);
                uint32_t bh[4];
                ldsm4(bh, bb + 8192 + boff);
                #pragma unroll
                for (int s = 0; s < 2; s++) {
                    mma_f16(acc[0][nh * 2 + s], ah0, bh[s * 2], bh[s * 2 + 1]);
                    mma_f16(acc[1][nh * 2 + s], ah1, bh[s * 2], bh[s * 2 + 1]);
                }
            }
        }
        stage = (stage == 5) ? 0 : stage + 1;
        nstage = (nstage == 5) ? 0 : nstage + 1;
    }

    #pragma unroll
    for (int mt = 0; mt < 2; mt++) {
        size_t rbase = row0 + wr * 32 + mt * 16 + (lane >> 2);
        #pragma unroll
        for (int nt = 0; nt < 8; nt++) {
            int col = m0 + wc * 64 + nt * 8 + (lane & 3) * 2;
            float b0 = bias[col], b1 = bias[col + 1];
            #pragma unroll
            for (int half = 0; half < 2; half++) {
                size_t row = rbase + half * 8;
                float v0 = acc[mt][nt][half * 2 + 0] + b0;
                float v1 = acc[mt][nt][half * 2 + 1] + b1;
                if (GELU) { v0 = v0 * normcdff(v0); v1 = v1 * normcdff(v1); }
                if (RES) {
                    float2 r2 = *reinterpret_cast<const float2*>(res + row * M + col);
                    v0 += r2.x; v1 += r2.y;
                }
                if (SPLIT == 2) {
                    *reinterpret_cast<__half2*>(Chi + row * M + col) = __floats2half2_rn(v0, v1);
                } else {
                    *reinterpret_cast<float2*>(C + row * M + col) = make_float2(v0, v1);
                }
            }
        }
    }
}

// ---------------- mma.sync causal flash attention: Q single plane, 2 CTAs/SM ----------
// smem: Qh [128][64] @0 (16KB); KV stages @16384: 2 x (Kh 8KB + Vh 8KB) = 32KB. 48KB tot.
#define ATT_SMEM 49152
#define SCALE_L2E 0.18033688f   // 0.125 * log2(e)

__global__ void __launch_bounds__(256, 2) attn_mma(const __half* __restrict__ qkvh,
                                                   __half* __restrict__ ohi) {
    extern __shared__ char smc[];
    uint32_t sb = smem_u32(smc);
    int t = threadIdx.x, lane = t & 31, w = t >> 5;
    int g = lane >> 3, l7 = lane & 7;
    int bh = blockIdx.y;
    int b = bh >> 4, h = bh & 15;
    int qt = (SEQ / 128 - 1) - blockIdx.x;
    int qb = qt * 128;
    size_t tok0 = (size_t)(b * SEQ + qb);

    // prologue: Q hi (1024 chunks) + KV tile 0 (1024 chunks)
    {
        #pragma unroll
        for (int i = 0; i < 4; i++) {
            int c = t + i * 256;
            int row = c >> 3, u = c & 7;
            uint32_t so = (uint32_t)(row * 128 + ((u ^ (row & 7)) << 4));
            const __half* gp = qkvh + (tok0 + row) * QKV_M + h * 64 + u * 8;
            cp16(sb + so, gp);
        }
        size_t ktok = (size_t)(b * SEQ);
        #pragma unroll
        for (int i = 0; i < 4; i++) {
            int c = t + i * 256;
            int plane = c >> 9, rem = c & 511;   // 0=K, 1=V
            int row = rem >> 3, u = rem & 7;
            uint32_t so = (uint32_t)(16384 + plane * 8192 + row * 128 + ((u ^ (row & 7)) << 4));
            const __half* gp = qkvh + (ktok + row) * QKV_M + 1024 + plane * 1024 + h * 64 + u * 8;
            cp16(sb + so, gp);
        }
        cp_commit();
    }

    uint32_t qah[4][4];
    float m0 = -1e30f, m1 = -1e30f, l0 = 0.f, l1 = 0.f;
    float o[8][4];
    #pragma unroll
    for (int j = 0; j < 8; j++)
        #pragma unroll
        for (int u = 0; u < 4; u++) o[j][u] = 0.f;

    int q0g = qb + w * 16 + (lane >> 2);
    int q1g = q0g + 8;

    int ntiles = 2 * qt + 2;
    for (int kt = 0; kt < ntiles; kt++) {
        int k0 = kt * 64;
        if (kt + 1 < ntiles) {
            uint32_t bufb = 16384u + (uint32_t)((kt + 1) & 1) * 16384u;
            size_t ktok = (size_t)(b * SEQ + (kt + 1) * 64);
            #pragma unroll
            for (int i = 0; i < 4; i++) {
                int c = t + i * 256;
                int plane = c >> 9, rem = c & 511;
                int row = rem >> 3, u = rem & 7;
                uint32_t so = bufb + (uint32_t)(plane * 8192 + row * 128 + ((u ^ (row & 7)) << 4));
                const __half* gp = qkvh + (ktok + row) * QKV_M + 1024 + plane * 1024 + h * 64 + u * 8;
                cp16(sb + so, gp);
            }
            cp_commit();
            cp_wait1();
        } else {
            cp_wait0();
        }
        __syncthreads();

        if (kt == 0) {
            int arow = w * 16 + (lane & 15);
            uint32_t aro = (uint32_t)(arow * 128);
            uint32_t asw = (uint32_t)(arow & 7);
            #pragma unroll
            for (int ks = 0; ks < 4; ks++) {
                uint32_t u = (uint32_t)(ks * 2) + (uint32_t)(lane >> 4);
                ldsm4(qah[ks], sb + aro + ((u ^ asw) << 4));
            }
        }

        uint32_t kvb = sb + 16384u + (uint32_t)(kt & 1) * 16384u;

        float s[8][4];
        #pragma unroll
        for (int j = 0; j < 8; j++)
            #pragma unroll
            for (int u = 0; u < 4; u++) s[j][u] = 0.f;

        #pragma unroll
        for (int nh = 0; nh < 4; nh++) {
            int brow = nh * 16 + ((g >> 1) << 3) + l7;
            uint32_t bro = (uint32_t)(brow * 128);
            uint32_t bsw = (uint32_t)(brow & 7);
            #pragma unroll
            for (int ks = 0; ks < 4; ks++) {
                uint32_t u = (uint32_t)(ks * 2) + (uint32_t)(g & 1);
                uint32_t off = bro + ((u ^ bsw) << 4);
                uint32_t bhf[4];
                ldsm4(bhf, kvb + off);
                mma_f16(s[nh * 2],     qah[ks], bhf[0], bhf[1]);
                mma_f16(s[nh * 2 + 1], qah[ks], bhf[2], bhf[3]);
            }
        }

        bool diag = (kt >= 2 * qt);
        float mx0 = -1e30f, mx1 = -1e30f;
        #pragma unroll
        for (int j = 0; j < 8; j++) {
            int kb = k0 + j * 8 + ((lane & 3) << 1);
            float y0 = s[j][0] * SCALE_L2E;
            float y1 = s[j][1] * SCALE_L2E;
            float y2 = s[j][2] * SCALE_L2E;
            float y3 = s[j][3] * SCALE_L2E;
            if (diag) {
                if (kb     > q0g) y0 = -1e30f;
                if (kb + 1 > q0g) y1 = -1e30f;
                if (kb     > q1g) y2 = -1e30f;
                if (kb + 1 > q1g) y3 = -1e30f;
            }
            s[j][0] = y0; s[j][1] = y1; s[j][2] = y2; s[j][3] = y3;
            mx0 = fmaxf(mx0, fmaxf(y0, y1));
            mx1 = fmaxf(mx1, fmaxf(y2, y3));
        }
        mx0 = fmaxf(mx0, __shfl_xor_sync(0xFFFFFFFFu, mx0, 1));
        mx0 = fmaxf(mx0, __shfl_xor_sync(0xFFFFFFFFu, mx0, 2));
        mx1 = fmaxf(mx1, __shfl_xor_sync(0xFFFFFFFFu, mx1, 1));
        mx1 = fmaxf(mx1, __shfl_xor_sync(0xFFFFFFFFu, mx1, 2));

        float m0n = fmaxf(m0, mx0), m1n = fmaxf(m1, mx1);
        float corr0 = fexp2(m0 - m0n), corr1 = fexp2(m1 - m1n);
        m0 = m0n; m1 = m1n;

        float rs0 = 0.f, rs1 = 0.f;
        #pragma unroll
        for (int j = 0; j < 8; j++) {
            float p0 = fexp2(s[j][0] - m0);
            float p1 = fexp2(s[j][1] - m0);
            float p2 = fexp2(s[j][2] - m1);
            float p3 = fexp2(s[j][3] - m1);
            s[j][0] = p0; s[j][1] = p1; s[j][2] = p2; s[j][3] = p3;
            rs0 += p0 + p1; rs1 += p2 + p3;
        }
        rs0 += __shfl_xor_sync(0xFFFFFFFFu, rs0, 1);
        rs0 += __shfl_xor_sync(0xFFFFFFFFu, rs0, 2);
        rs1 += __shfl_xor_sync(0xFFFFFFFFu, rs1, 1);
        rs1 += __shfl_xor_sync(0xFFFFFFFFu, rs1, 2);
        l0 = l0 * corr0 + rs0;
        l1 = l1 * corr1 + rs1;
        #pragma unroll
        for (int j = 0; j < 8; j++) {
            o[j][0] *= corr0; o[j][1] *= corr0;
            o[j][2] *= corr1; o[j][3] *= corr1;
        }

        #pragma unroll
        for (int ks2 = 0; ks2 < 4; ks2++) {
            int j0 = ks2 * 2, j1 = j0 + 1;
            uint32_t aPh[4];
            aPh[0] = f2h2(s[j0][0], s[j0][1]);
            aPh[1] = f2h2(s[j0][2], s[j0][3]);
            aPh[2] = f2h2(s[j1][0], s[j1][1]);
            aPh[3] = f2h2(s[j1][2], s[j1][3]);

            int vrow = ks2 * 16 + ((g & 1) << 3) + l7;
            uint32_t vro = (uint32_t)(vrow * 128);
            uint32_t vsw = (uint32_t)(vrow & 7);
            #pragma unroll
            for (int dh = 0; dh < 4; dh++) {
                uint32_t u = (uint32_t)(dh * 2) + (uint32_t)(g >> 1);
                uint32_t off = vro + ((u ^ vsw) << 4);
                uint32_t vhf[4];
                ldsm4t(vhf, kvb + 8192 + off);
                mma_f16(o[dh * 2],     aPh, vhf[0], vhf[1]);
                mma_f16(o[dh * 2 + 1], aPh, vhf[2], vhf[3]);
            }
        }
        __syncthreads();
    }

    float inv0 = 1.0f / l0, inv1 = 1.0f / l1;
    size_t r0o = ((size_t)(b * SEQ) + q0g) * DMODEL + h * 64;
    size_t r1o = ((size_t)(b * SEQ) + q1g) * DMODEL + h * 64;
    #pragma unroll
    for (int j = 0; j < 8; j++) {
        int col = j * 8 + (lane & 3) * 2;
        *reinterpret_cast<__half2*>(ohi + r0o + col) =
            __floats2half2_rn(o[j][0] * inv0, o[j][1] * inv0);
        *reinterpret_cast<__half2*>(ohi + r1o + col) =
            __floats2half2_rn(o[j][2] * inv1, o[j][3] * inv1);
    }
}

// ---------------- launch ----------------
extern "C" void kernel_launch(void* const* d_in, const int* in_sizes, int n_in,
                              void* d_out, int out_size) {
    const float* x    = (const float*)d_in[0];
    const float* ln1g = (const float*)d_in[1];
    const float* ln1b = (const float*)d_in[2];
    const float* Wq   = (const float*)d_in[3];
    const float* bq   = (const float*)d_in[4];
    const float* Wk   = (const float*)d_in[5];
    const float* bk   = (const float*)d_in[6];
    const float* Wv   = (const float*)d_in[7];
    const float* bv   = (const float*)d_in[8];
    const float* Wo   = (const float*)d_in[9];
    const float* bo   = (const float*)d_in[10];
    const float* ln2g = (const float*)d_in[11];
    const float* ln2b = (const float*)d_in[12];
    const float* W1   = (const float*)d_in[13];
    const float* b1   = (const float*)d_in[14];
    const float* W2   = (const float*)d_in[15];
    const float* b2   = (const float*)d_in[16];
    float* out = (float*)d_out;

    __half *w, *hh, *qkvh, *oh, *fh;
    float *x1, *b3;
    cudaGetSymbolAddress((void**)&w,    g_w);
    cudaGetSymbolAddress((void**)&hh,   g_hh);
    cudaGetSymbolAddress((void**)&qkvh, g_qkvh);
    cudaGetSymbolAddress((void**)&oh,   g_oh);
    cudaGetSymbolAddress((void**)&fh,   g_fh);
    cudaGetSymbolAddress((void**)&x1,   g_x1);
    cudaGetSymbolAddress((void**)&b3,   g_b3);

    static int attr_set = 0;
    if (!attr_set) {
        cudaFuncSetAttribute(attn_mma, cudaFuncAttributeMaxDynamicSharedMemorySize, ATT_SMEM);
        cudaFuncSetAttribute(gemm_qkv4, cudaFuncAttributeMaxDynamicSharedMemorySize, GEMM_SMEM);
        cudaFuncSetAttribute(gemm_mma<0, 1, 0>, cudaFuncAttributeMaxDynamicSharedMemorySize, GEMM_SMEM);
        cudaFuncSetAttribute(gemm_mma<1, 0, 2>, cudaFuncAttributeMaxDynamicSharedMemorySize, GEMM_SMEM);
        attr_set = 1;
    }

    wsplit_all<<<12288, 256>>>(Wq, Wk, Wv, Wo, W1, W2, w);
    biascat_kernel<<<12, 256>>>(bq, bk, bv, b3);

    // --- attention sublayer ---
    ln_kernel<<<N_TOK, 256>>>(x, ln1g, ln1b, hh);
    gemm_qkv4<<<dim3(QKV_M / 128, 32), 128, GEMM_SMEM>>>(
        hh, w + WQO, b3, qkvh, DMODEL, QKV_M);
    attn_mma<<<dim3(SEQ / 128, NHEAD * BATCH), 256, ATT_SMEM>>>(qkvh, oh);
    gemm_mma<0, 1, 0><<<dim3(8, 32), 256, GEMM_SMEM>>>(
        oh, w + WOO, bo, x, x1, nullptr, DMODEL, DMODEL);

    // --- FFN sublayer ---
    ln_kernel<<<N_TOK, 256>>>(x1, ln2g, ln2b, hh);
    gemm_mma<1, 0, 2><<<dim3(32, 32), 256, GEMM_SMEM>>>(
        hh, w + W1O, b1, nullptr, nullptr, fh, DMODEL, DFF);
    gemm_mma<0, 1, 0><<<dim3(8, 32), 256, GEMM_SMEM>>>(
        fh, w + W2O, b2, x1, out, nullptr, DFF, DMODEL);
}